// round 13
// baseline (speedup 1.0000x reference)
#include <cuda_runtime.h>
#include <cuda_fp16.h>

#define NN 32
#define CC 64
#define OO 64
#define TT 512
#define VV 25
#define SS 3
#define RR 32
#define EPSV 1e-5f
#define TB 8            // t-tile per block
#define NTB (TT/TB)     // 64
#define TVW (TB*VV)     // 200
#define UPAD 32         // att u-row pad -> 128B line-aligned LDG.128
#define AOS (VV*UPAD)   // 800 floats per (n,s,o)
#define VTS 10          // vT row stride: [v][t] stride 10 (<=2-way dump conflicts)
#define OSTR (VV*VTS)   // 250 floats per o in vt
#define OHALF 32        // o's per block

// ---- scratch ----
__device__ __align__(16) float g_xm[NN*CC*VV];
__device__ __align__(16) float g_att[NN*SS*OO*AOS];   // transposed [v][u], pads zero
__device__ __align__(16) float g_ybias[NN*OO*VV];
__device__ __align__(16) float g_w3t[SS*CC*OO];       // [s][c][o] (memcpy src)
__device__ __align__(16) __half g_yh[NN*OO*TT*VV];    // y in fp16
__device__ float g_sum[OO], g_sumsq[OO];

// w3 transposed, served from the constant port (off L1TEX)
__constant__ __align__(16) float c_w3t[SS*CC*OO];     // 48 KB

// ---- f32x2 helpers ----
typedef unsigned long long ull;
__device__ __forceinline__ ull pk2(float a, float b) {
    ull r; asm("mov.b64 %0, {%1, %2};" : "=l"(r) : "f"(a), "f"(b)); return r;
}
__device__ __forceinline__ void upk2(ull p, float& a, float& b) {
    asm("mov.b64 {%0, %1}, %2;" : "=f"(a), "=f"(b) : "l"(p));
}
__device__ __forceinline__ ull fma2(ull a, ull b, ull c) {
    ull d; asm("fma.rn.f32x2 %0, %1, %2, %3;" : "=l"(d) : "l"(a), "l"(b), "l"(c)); return d;
}

// ---------------------------------------------------------------------------
// Kernel 1: xm mean over T (coalesced, warp-per-t-chunk); also transposes w3.
// ---------------------------------------------------------------------------
__global__ void k_xm(const float* __restrict__ x, const float* __restrict__ w3) {
    int bid = blockIdx.x;              // (n*CC + c), 2048 blocks
    int tid = threadIdx.x, w = tid >> 5, lane = tid & 31;

    if (bid < 48) {                    // 48*256 = SS*CC*OO exactly
        int idx = bid*256 + tid;
        int o = idx % OO, c = (idx / OO) % CC, s = idx / (OO*CC);
        g_w3t[idx] = w3[(s*OO + o)*CC + c];
    }

    __shared__ float part[8][VV];
    const float* base = x + (size_t)bid * (TT*VV);
    if (lane < VV) {
        const float* p = base + (w*64)*VV + lane;
        float a0=0.f, a1=0.f, a2=0.f, a3=0.f;
        #pragma unroll 4
        for (int t = 0; t < 64; t += 4) {
            a0 += p[(t+0)*VV]; a1 += p[(t+1)*VV];
            a2 += p[(t+2)*VV]; a3 += p[(t+3)*VV];
        }
        part[w][lane] = (a0+a1)+(a2+a3);
    }
    __syncthreads();
    if (tid < VV) {
        float s2 = 0.f;
        #pragma unroll
        for (int ww = 0; ww < 8; ww++) s2 += part[ww][tid];
        g_xm[bid*VV + tid] = s2 * (1.0f/(float)TT);
    }
}

// ---------------------------------------------------------------------------
// Kernel 2 (o-split x4): attention tensor, transposed+padded g_att[(nso)][v*32+u]
// ---------------------------------------------------------------------------
#define OSL 16
__global__ void k_att(const float* __restrict__ w1, const float* __restrict__ b1,
                      const float* __restrict__ w2, const float* __restrict__ b2,
                      const float* __restrict__ w4, const float* __restrict__ b4,
                      const float* __restrict__ alpha, const float* __restrict__ A) {
    int og = blockIdx.x & 3;
    int ns = blockIdx.x >> 2;
    int n = ns / SS, s = ns % SS;
    __shared__ float xm_sm[CC*VV];
    __shared__ float q_sm[RR*VV];
    __shared__ float k_sm[RR*VV];
    __shared__ float w4_sm[OSL*RR];
    __shared__ float b4_sm[OSL];
    int tid = threadIdx.x;

    for (int i = tid; i < CC*VV; i += blockDim.x) xm_sm[i] = g_xm[n*CC*VV + i];
    for (int i = tid; i < OSL*RR; i += blockDim.x) w4_sm[i] = w4[s*OO*RR + og*OSL*RR + i];
    if (tid < OSL) b4_sm[tid] = b4[s*OO + og*OSL + tid];
    __syncthreads();

    for (int e = tid; e < RR*VV; e += blockDim.x) {
        int r = e / VV, v = e % VV;
        const float* w1r = w1 + (s*RR + r)*CC;
        const float* w2r = w2 + (s*RR + r)*CC;
        float accq = b1[s*RR + r], acck = b2[s*RR + r];
        #pragma unroll 8
        for (int c = 0; c < CC; c++) {
            float xv = xm_sm[c*VV + v];
            accq = fmaf(w1r[c], xv, accq);
            acck = fmaf(w2r[c], xv, acck);
        }
        q_sm[e] = accq; k_sm[e] = acck;
    }
    __syncthreads();

    float al = alpha[s];
    for (int uv = tid; uv < VV*VV; uv += blockDim.x) {
        int u = uv / VV, v = uv % VV;
        float rel[RR];
        #pragma unroll
        for (int r = 0; r < RR; r++)
            rel[r] = fmaxf(q_sm[r*VV + u] - k_sm[r*VV + v], 0.f);
        float Auv = A[(s*VV + u)*VV + v];
        float* outp = g_att + (size_t)((n*SS + s)*OO + og*OSL) * AOS + v*UPAD + u;
        for (int o = 0; o < OSL; o++) {
            float acc = 0.f;
            #pragma unroll
            for (int r = 0; r < RR; r++)
                acc = fmaf(w4_sm[o*RR + r], rel[r], acc);
            outp[o*AOS] = al*(acc + b4_sm[o]) + Auv;
        }
    }
}

// ---------------------------------------------------------------------------
// Kernel 3: ybias via one warp per (n,o), fully coalesced; zeroes BN stats.
// ---------------------------------------------------------------------------
__global__ void k_ybias(const float* __restrict__ b3) {
    int n   = blockIdx.x >> 3;
    int oct = blockIdx.x & 7;
    int tid = threadIdx.x, w = tid >> 5, lane = tid & 31;
    if (blockIdx.x == 0) {
        if (tid < OO)             g_sum[tid] = 0.f;
        else if (tid < 2*OO)      g_sumsq[tid - OO] = 0.f;
    }
    int o = oct*8 + w;
    float acc = 0.f;
    #pragma unroll
    for (int s = 0; s < SS; s++) {
        const float* ap = g_att + (size_t)((n*SS + s)*OO + o) * AOS + lane;
        float rs = 0.f;
        #pragma unroll
        for (int v = 0; v < VV; v++) rs += ap[v*UPAD];
        acc = fmaf(b3[s*OO + o], rs, acc);
    }
    if (lane < VV) g_ybias[(n*OO + o)*VV + lane] = acc;
}

// ---------------------------------------------------------------------------
// Kernel 4 (main): round-9 blocking UNCHANGED; x staged in SMEM as fp16.
// smem 57.6 KB -> 3 blocks/SM (24 warps, was 16), launch_bounds(256,3).
// v-stage: 2 LDS.32 (half2) + 4 cvt + 16 f32x2 per c, w3 via constant port.
// y-stage: 4 oq att LDG.128 streams (unchanged). fp16 y epilogue (unchanged).
// ---------------------------------------------------------------------------
#define SM_XS_B (CC*TVW*2)          // 25600 B (fp16 x tile)
#define SM_VT_B (OHALF*OSTR*4)      // 32000 B
#define SMEM_BYTES (SM_XS_B + SM_VT_B)   // 57600 B

__global__ void __launch_bounds__(256, 3)
k_main(const float* __restrict__ x) {
    extern __shared__ char smb[];
    __half* xs = (__half*)smb;
    float*  vt = (float*)(smb + SM_XS_B);

    int rem  = blockIdx.x % (NTB*2);
    int n    = blockIdx.x / (NTB*2);
    int tb   = rem >> 1;
    int obase = (rem & 1) * OHALF;
    int t0 = tb * TB;
    int tid = threadIdx.x, w = tid >> 5, lane = tid & 31;

    // stage x tile [c][200] as fp16 (8B per 4 elements)
    uint2* xsq = (uint2*)xs;
    for (int i = tid; i < CC*50; i += 256) {
        int c = i / 50, qd = i % 50;
        float4 f = *(const float4*)(x + (size_t)(n*CC + c)*(TT*VV) + t0*VV + qd*4);
        __half2 h0 = __floats2half2_rn(f.x, f.y);
        __half2 h1 = __floats2half2_rn(f.z, f.w);
        uint2 pk;
        pk.x = *reinterpret_cast<unsigned*>(&h0);
        pk.y = *reinterpret_cast<unsigned*>(&h1);
        xsq[c*50 + qd] = pk;
    }

    // ---- v-stage lane constants (octet q, half h) ----
    int q = w & 3, h = w >> 2;
    bool hasB = (lane < 18);
    int offA = 100*h + 2*lane;
    int offB = hasB ? (offA + 64) : offA;
    int tvA  = offA;
    int tvB  = offA + 64;
    int sA0 = (tvA % VV)*VTS + tvA/VV;
    int sA1 = ((tvA+1) % VV)*VTS + (tvA+1)/VV;
    int sB0 = hasB ? ((tvB % VV)*VTS + tvB/VV) : 0;
    int sB1 = hasB ? (((tvB+1) % VV)*VTS + (tvB+1)/VV) : 0;

    // ---- y-stage lane constants ----
    int tp = lane >> 3, ug = lane & 7;

    // persistent y acc (f32x2 over u-pairs), init with ybias
    ull acc2[4][2][2];
    #pragma unroll
    for (int oq = 0; oq < 4; oq++) {
        const float* yb = g_ybias + (size_t)(n*OO + obase + 4*w + oq)*VV;
        #pragma unroll
        for (int p = 0; p < 2; p++) {
            int u0 = 4*ug + 2*p;
            float y0 = (u0   < VV) ? yb[u0]   : 0.f;
            float y1 = (u0+1 < VV) ? yb[u0+1] : 0.f;
            ull ybp = pk2(y0, y1);
            acc2[oq][0][p] = ybp; acc2[oq][1][p] = ybp;
        }
    }
    __syncthreads();

    for (int s = 0; s < SS; s++) {
        // ---- v-stage: 8 o's x 2 tv-pairs; w3 via constant port ----
        ull acc[8][2];
        #pragma unroll
        for (int i = 0; i < 8; i++) { acc[i][0] = 0ull; acc[i][1] = 0ull; }

        int wbase = (s*CC)*OO + obase + 8*q;
        #pragma unroll 4
        for (int c = 0; c < CC; c++) {
            float4 wA4 = *(const float4*)(c_w3t + wbase + c*OO);
            float4 wB4 = *(const float4*)(c_w3t + wbase + c*OO + 4);
            const __half* xr = xs + c*TVW;
            __half2 hA = *(const __half2*)(xr + offA);
            __half2 hB = *(const __half2*)(xr + offB);
            float2 fA = __half22float2(hA);
            float2 fB = __half22float2(hB);
            ull xA = pk2(fA.x, fA.y);
            ull xB = pk2(fB.x, fB.y);
            ull w0 = pk2(wA4.x, wA4.x), w1 = pk2(wA4.y, wA4.y);
            ull w2 = pk2(wA4.z, wA4.z), w3s = pk2(wA4.w, wA4.w);
            ull w4s = pk2(wB4.x, wB4.x), w5 = pk2(wB4.y, wB4.y);
            ull w6 = pk2(wB4.z, wB4.z), w7 = pk2(wB4.w, wB4.w);
            acc[0][0]=fma2(w0,xA,acc[0][0]);  acc[0][1]=fma2(w0,xB,acc[0][1]);
            acc[1][0]=fma2(w1,xA,acc[1][0]);  acc[1][1]=fma2(w1,xB,acc[1][1]);
            acc[2][0]=fma2(w2,xA,acc[2][0]);  acc[2][1]=fma2(w2,xB,acc[2][1]);
            acc[3][0]=fma2(w3s,xA,acc[3][0]); acc[3][1]=fma2(w3s,xB,acc[3][1]);
            acc[4][0]=fma2(w4s,xA,acc[4][0]); acc[4][1]=fma2(w4s,xB,acc[4][1]);
            acc[5][0]=fma2(w5,xA,acc[5][0]);  acc[5][1]=fma2(w5,xB,acc[5][1]);
            acc[6][0]=fma2(w6,xA,acc[6][0]);  acc[6][1]=fma2(w6,xB,acc[6][1]);
            acc[7][0]=fma2(w7,xA,acc[7][0]);  acc[7][1]=fma2(w7,xB,acc[7][1]);
        }

        __syncthreads();   // prior y-stage reads of vt complete
        // ---- dump vT[o_loc][v][t] ----
        #pragma unroll
        for (int i = 0; i < 8; i++) {
            float* d = vt + (8*q + i) * OSTR;
            float lo, hi;
            upk2(acc[i][0], lo, hi);
            d[sA0] = lo; d[sA1] = hi;
            if (hasB) {
                upk2(acc[i][1], lo, hi);
                d[sB0] = lo; d[sB1] = hi;
            }
        }
        __syncthreads();

        // ---- y-stage: all 4 oq interleaved -> 4 independent att streams ----
        const float* dvp0 = vt + (4*w + 0)*OSTR + 2*tp;
        const float* dvp1 = vt + (4*w + 1)*OSTR + 2*tp;
        const float* dvp2 = vt + (4*w + 2)*OSTR + 2*tp;
        const float* dvp3 = vt + (4*w + 3)*OSTR + 2*tp;
        const float* agb = g_att + (size_t)((n*SS + s)*OO + obase + 4*w)*AOS + 4*ug;
        #pragma unroll
        for (int v = 0; v < VV; v++) {
            ulonglong2 at0 = *(const ulonglong2*)(agb + 0*AOS + v*UPAD);
            ulonglong2 at1 = *(const ulonglong2*)(agb + 1*AOS + v*UPAD);
            ulonglong2 at2 = *(const ulonglong2*)(agb + 2*AOS + v*UPAD);
            ulonglong2 at3 = *(const ulonglong2*)(agb + 3*AOS + v*UPAD);
            float2 vb0 = *(const float2*)(dvp0 + v*VTS);
            float2 vb1 = *(const float2*)(dvp1 + v*VTS);
            float2 vb2 = *(const float2*)(dvp2 + v*VTS);
            float2 vb3 = *(const float2*)(dvp3 + v*VTS);

            ull va, vbb;
            va = pk2(vb0.x, vb0.x); vbb = pk2(vb0.y, vb0.y);
            acc2[0][0][0] = fma2(at0.x, va,  acc2[0][0][0]);
            acc2[0][0][1] = fma2(at0.y, va,  acc2[0][0][1]);
            acc2[0][1][0] = fma2(at0.x, vbb, acc2[0][1][0]);
            acc2[0][1][1] = fma2(at0.y, vbb, acc2[0][1][1]);
            va = pk2(vb1.x, vb1.x); vbb = pk2(vb1.y, vb1.y);
            acc2[1][0][0] = fma2(at1.x, va,  acc2[1][0][0]);
            acc2[1][0][1] = fma2(at1.y, va,  acc2[1][0][1]);
            acc2[1][1][0] = fma2(at1.x, vbb, acc2[1][1][0]);
            acc2[1][1][1] = fma2(at1.y, vbb, acc2[1][1][1]);
            va = pk2(vb2.x, vb2.x); vbb = pk2(vb2.y, vb2.y);
            acc2[2][0][0] = fma2(at2.x, va,  acc2[2][0][0]);
            acc2[2][0][1] = fma2(at2.y, va,  acc2[2][0][1]);
            acc2[2][1][0] = fma2(at2.x, vbb, acc2[2][1][0]);
            acc2[2][1][1] = fma2(at2.y, vbb, acc2[2][1][1]);
            va = pk2(vb3.x, vb3.x); vbb = pk2(vb3.y, vb3.y);
            acc2[3][0][0] = fma2(at3.x, va,  acc2[3][0][0]);
            acc2[3][0][1] = fma2(at3.y, va,  acc2[3][0][1]);
            acc2[3][1][0] = fma2(at3.x, vbb, acc2[3][1][0]);
            acc2[3][1][1] = fma2(at3.y, vbb, acc2[3][1][1]);
        }
    }

    // ---- epilogue: write y (fp16), accumulate BN stats (fp32 exact) ----
    #pragma unroll
    for (int oq = 0; oq < 4; oq++) {
        int o = obase + 4*w + oq;
        float ps = 0.f, pss = 0.f;
        #pragma unroll
        for (int j = 0; j < 2; j++) {
            int t = 2*tp + j;
            float uv0, uv1, uv2, uv3;
            upk2(acc2[oq][j][0], uv0, uv1);
            upk2(acc2[oq][j][1], uv2, uv3);
            float vals[4] = {uv0, uv1, uv2, uv3};
            __half* yp = g_yh + ((size_t)(n*OO + o)*TT + t0 + t)*VV;
            #pragma unroll
            for (int i = 0; i < 4; i++) {
                int u = 4*ug + i;
                if (u < VV) {
                    yp[u] = __float2half(vals[i]);
                    ps  += vals[i];
                    pss += vals[i]*vals[i];
                }
            }
        }
        #pragma unroll
        for (int off = 16; off > 0; off >>= 1) {
            ps  += __shfl_xor_sync(0xffffffffu, ps,  off);
            pss += __shfl_xor_sync(0xffffffffu, pss, off);
        }
        if (lane == 0) {
            atomicAdd(&g_sum[o],   ps);
            atomicAdd(&g_sumsq[o], pss);
        }
    }
}

// ---------------------------------------------------------------------------
// Kernel 5: out = relu(y) + y*scale + shift + x (BN params derived in-block).
// ---------------------------------------------------------------------------
__global__ void k_final(const float* __restrict__ x, float* __restrict__ out,
                        const float* __restrict__ gamma, const float* __restrict__ beta) {
    __shared__ float s_sc[OO], s_sh[OO];
    int tid = threadIdx.x;
    if (tid < OO) {
        float cnt = (float)(NN*TT*VV);
        float mu  = g_sum[tid] / cnt;
        float var = g_sumsq[tid] / cnt - mu*mu;
        float sc  = gamma[tid] * rsqrtf(var + EPSV);
        s_sc[tid] = sc;
        s_sh[tid] = beta[tid] - mu*sc;
    }
    __syncthreads();

    const int total4 = NN*OO*TT*VV / 4;
    for (int i = blockIdx.x*blockDim.x + tid; i < total4; i += gridDim.x*blockDim.x) {
        int c = (i / (TT*VV/4)) % OO;
        float sc = s_sc[c], sh = s_sh[c];
        uint2 raw = ((const uint2*)g_yh)[i];      // 4 halves, 8B aligned
        __half2 h0 = *reinterpret_cast<__half2*>(&raw.x);
        __half2 h1 = *reinterpret_cast<__half2*>(&raw.y);
        float2 f0 = __half22float2(h0);
        float2 f1 = __half22float2(h1);
        float4 x4 = ((const float4*)x)[i];
        float4 r;
        r.x = fmaxf(f0.x, 0.f) + fmaf(f0.x, sc, sh) + x4.x;
        r.y = fmaxf(f0.y, 0.f) + fmaf(f0.y, sc, sh) + x4.y;
        r.z = fmaxf(f1.x, 0.f) + fmaf(f1.x, sc, sh) + x4.z;
        r.w = fmaxf(f1.y, 0.f) + fmaf(f1.y, sc, sh) + x4.w;
        ((float4*)out)[i] = r;
    }
}

// ---------------------------------------------------------------------------
extern "C" void kernel_launch(void* const* d_in, const int* in_sizes, int n_in,
                              void* d_out, int out_size) {
    (void)in_sizes; (void)n_in; (void)out_size;
    const float* x     = (const float*)d_in[0];
    const float* A     = (const float*)d_in[1];
    const float* w1    = (const float*)d_in[2];
    const float* b1    = (const float*)d_in[3];
    const float* w2    = (const float*)d_in[4];
    const float* b2    = (const float*)d_in[5];
    const float* w3    = (const float*)d_in[6];
    const float* b3    = (const float*)d_in[7];
    const float* w4    = (const float*)d_in[8];
    const float* b4    = (const float*)d_in[9];
    const float* alpha = (const float*)d_in[10];
    const float* gamma = (const float*)d_in[11];
    const float* beta  = (const float*)d_in[12];
    float* out = (float*)d_out;

    cudaFuncSetAttribute(k_main, cudaFuncAttributeMaxDynamicSharedMemorySize, SMEM_BYTES);

    void* w3t_dev = nullptr;
    cudaGetSymbolAddress(&w3t_dev, g_w3t);

    k_xm   <<< NN*CC, 256 >>>(x, w3);
    cudaMemcpyToSymbolAsync(c_w3t, w3t_dev, SS*CC*OO*sizeof(float), 0,
                            cudaMemcpyDeviceToDevice, 0);
    k_att  <<< NN*SS*4, 256 >>>(w1, b1, w2, b2, w4, b4, alpha, A);
    k_ybias<<< NN*8, 256 >>>(b3);
    k_main <<< NN*NTB*2, 256, SMEM_BYTES >>>(x);
    k_final<<< 4096, 256 >>>(x, out, gamma, beta);
}

// round 14
// speedup vs baseline: 1.0815x; 1.0815x over previous
#include <cuda_runtime.h>
#include <cuda_fp16.h>

#define NN 32
#define CC 64
#define OO 64
#define TT 512
#define VV 25
#define SS 3
#define RR 32
#define EPSV 1e-5f
#define TB 8            // t-tile per block
#define NTB (TT/TB)     // 64
#define TVW (TB*VV)     // 200
#define UPAD 32         // att u-row pad (32 halves = 64B rows)
#define AOS (VV*UPAD)   // 800 halves per (n,s,o)
#define VTS 10          // vT row stride: [v][t] stride 10 (<=2-way dump conflicts)
#define OSTR (VV*VTS)   // 250 floats per o in vt
#define OHALF 32        // o's per block

// ---- scratch ----
__device__ __align__(16) float  g_xm[NN*CC*VV];
__device__ __align__(16) __half g_atth[NN*SS*OO*AOS]; // att fp16, transposed [v][u]
__device__ __align__(16) float  g_ybias[NN*OO*VV];
__device__ __align__(16) float  g_w3t[SS*CC*OO];      // [s][c][o] (memcpy src)
__device__ __align__(16) __half g_yh[NN*OO*TT*VV];    // y in fp16
__device__ float g_sum[OO], g_sumsq[OO];

// w3 transposed, served from the constant port (off L1TEX)
__constant__ __align__(16) float c_w3t[SS*CC*OO];     // 48 KB

// ---- f32x2 helpers ----
typedef unsigned long long ull;
__device__ __forceinline__ ull pk2(float a, float b) {
    ull r; asm("mov.b64 %0, {%1, %2};" : "=l"(r) : "f"(a), "f"(b)); return r;
}
__device__ __forceinline__ void upk2(ull p, float& a, float& b) {
    asm("mov.b64 {%0, %1}, %2;" : "=f"(a), "=f"(b) : "l"(p));
}
__device__ __forceinline__ ull fma2(ull a, ull b, ull c) {
    ull d; asm("fma.rn.f32x2 %0, %1, %2, %3;" : "=l"(d) : "l"(a), "l"(b), "l"(c)); return d;
}
// half2 (as uint) -> packed f32x2
__device__ __forceinline__ ull h2f2(unsigned h) {
    __half2 hh = *reinterpret_cast<__half2*>(&h);
    float2 f = __half22float2(hh);
    return pk2(f.x, f.y);
}

// ---------------------------------------------------------------------------
// Kernel 1: xm mean over T (coalesced, warp-per-t-chunk); also transposes w3.
// ---------------------------------------------------------------------------
__global__ void k_xm(const float* __restrict__ x, const float* __restrict__ w3) {
    int bid = blockIdx.x;              // (n*CC + c), 2048 blocks
    int tid = threadIdx.x, w = tid >> 5, lane = tid & 31;

    if (bid < 48) {                    // 48*256 = SS*CC*OO exactly
        int idx = bid*256 + tid;
        int o = idx % OO, c = (idx / OO) % CC, s = idx / (OO*CC);
        g_w3t[idx] = w3[(s*OO + o)*CC + c];
    }

    __shared__ float part[8][VV];
    const float* base = x + (size_t)bid * (TT*VV);
    if (lane < VV) {
        const float* p = base + (w*64)*VV + lane;
        float a0=0.f, a1=0.f, a2=0.f, a3=0.f;
        #pragma unroll 4
        for (int t = 0; t < 64; t += 4) {
            a0 += p[(t+0)*VV]; a1 += p[(t+1)*VV];
            a2 += p[(t+2)*VV]; a3 += p[(t+3)*VV];
        }
        part[w][lane] = (a0+a1)+(a2+a3);
    }
    __syncthreads();
    if (tid < VV) {
        float s2 = 0.f;
        #pragma unroll
        for (int ww = 0; ww < 8; ww++) s2 += part[ww][tid];
        g_xm[bid*VV + tid] = s2 * (1.0f/(float)TT);
    }
}

// ---------------------------------------------------------------------------
// Kernel 2 (o-split x4): attention tensor -> fp16, transposed+padded
// ---------------------------------------------------------------------------
#define OSL 16
__global__ void k_att(const float* __restrict__ w1, const float* __restrict__ b1,
                      const float* __restrict__ w2, const float* __restrict__ b2,
                      const float* __restrict__ w4, const float* __restrict__ b4,
                      const float* __restrict__ alpha, const float* __restrict__ A) {
    int og = blockIdx.x & 3;
    int ns = blockIdx.x >> 2;
    int n = ns / SS, s = ns % SS;
    __shared__ float xm_sm[CC*VV];
    __shared__ float q_sm[RR*VV];
    __shared__ float k_sm[RR*VV];
    __shared__ float w4_sm[OSL*RR];
    __shared__ float b4_sm[OSL];
    int tid = threadIdx.x;

    for (int i = tid; i < CC*VV; i += blockDim.x) xm_sm[i] = g_xm[n*CC*VV + i];
    for (int i = tid; i < OSL*RR; i += blockDim.x) w4_sm[i] = w4[s*OO*RR + og*OSL*RR + i];
    if (tid < OSL) b4_sm[tid] = b4[s*OO + og*OSL + tid];
    __syncthreads();

    for (int e = tid; e < RR*VV; e += blockDim.x) {
        int r = e / VV, v = e % VV;
        const float* w1r = w1 + (s*RR + r)*CC;
        const float* w2r = w2 + (s*RR + r)*CC;
        float accq = b1[s*RR + r], acck = b2[s*RR + r];
        #pragma unroll 8
        for (int c = 0; c < CC; c++) {
            float xv = xm_sm[c*VV + v];
            accq = fmaf(w1r[c], xv, accq);
            acck = fmaf(w2r[c], xv, acck);
        }
        q_sm[e] = accq; k_sm[e] = acck;
    }
    __syncthreads();

    float al = alpha[s];
    for (int uv = tid; uv < VV*VV; uv += blockDim.x) {
        int u = uv / VV, v = uv % VV;
        float rel[RR];
        #pragma unroll
        for (int r = 0; r < RR; r++)
            rel[r] = fmaxf(q_sm[r*VV + u] - k_sm[r*VV + v], 0.f);
        float Auv = A[(s*VV + u)*VV + v];
        __half* outp = g_atth + (size_t)((n*SS + s)*OO + og*OSL) * AOS + v*UPAD + u;
        for (int o = 0; o < OSL; o++) {
            float acc = 0.f;
            #pragma unroll
            for (int r = 0; r < RR; r++)
                acc = fmaf(w4_sm[o*RR + r], rel[r], acc);
            outp[o*AOS] = __float2half(al*(acc + b4_sm[o]) + Auv);
        }
    }
}

// ---------------------------------------------------------------------------
// Kernel 3: ybias via one warp per (n,o), fully coalesced; zeroes BN stats.
// ---------------------------------------------------------------------------
__global__ void k_ybias(const float* __restrict__ b3) {
    int n   = blockIdx.x >> 3;
    int oct = blockIdx.x & 7;
    int tid = threadIdx.x, w = tid >> 5, lane = tid & 31;
    if (blockIdx.x == 0) {
        if (tid < OO)             g_sum[tid] = 0.f;
        else if (tid < 2*OO)      g_sumsq[tid - OO] = 0.f;
    }
    int o = oct*8 + w;
    float acc = 0.f;
    #pragma unroll
    for (int s = 0; s < SS; s++) {
        const __half* ap = g_atth + (size_t)((n*SS + s)*OO + o) * AOS + lane;
        float rs = 0.f;
        #pragma unroll
        for (int v = 0; v < VV; v++) rs += __half2float(ap[v*UPAD]);
        acc = fmaf(b3[s*OO + o], rs, acc);
    }
    if (lane < VV) g_ybias[(n*OO + o)*VV + lane] = acc;
}

// ---------------------------------------------------------------------------
// Kernel 4 (main): EXACT round-12 structure (fp32 xs, 2 blocks/SM, 519.6us);
// only the y-stage att loads are fp16 now (LDG.64 + 2 cvt per oq per v).
// ---------------------------------------------------------------------------
#define SM_XS (CC*TVW)          // 12800 floats
#define SM_VT (OHALF*OSTR)      // 8000 floats
#define SMEM_FLOATS (SM_XS + SM_VT)   // 20800 floats = 83,200 B

__global__ void __launch_bounds__(256, 2)
k_main(const float* __restrict__ x) {
    extern __shared__ float sm[];
    float* xs = sm;
    float* vt = sm + SM_XS;

    int rem  = blockIdx.x % (NTB*2);
    int n    = blockIdx.x / (NTB*2);
    int tb   = rem >> 1;
    int obase = (rem & 1) * OHALF;
    int t0 = tb * TB;
    int tid = threadIdx.x, w = tid >> 5, lane = tid & 31;

    // stage x tile [c][200] (fp32, as in round 12)
    float4* xs4 = (float4*)xs;
    for (int i = tid; i < CC*50; i += 256) {
        int c = i / 50, qd = i % 50;
        xs4[c*50 + qd] = *(const float4*)(x + (size_t)(n*CC + c)*(TT*VV) + t0*VV + qd*4);
    }

    // ---- v-stage lane constants (octet q, half h) ----
    int q = w & 3, h = w >> 2;
    bool hasB = (lane < 18);
    int offA = 100*h + 2*lane;
    int offB = hasB ? (offA + 64) : offA;
    int tvA  = offA;
    int tvB  = offA + 64;
    int sA0 = (tvA % VV)*VTS + tvA/VV;
    int sA1 = ((tvA+1) % VV)*VTS + (tvA+1)/VV;
    int sB0 = hasB ? ((tvB % VV)*VTS + tvB/VV) : 0;
    int sB1 = hasB ? (((tvB+1) % VV)*VTS + (tvB+1)/VV) : 0;

    // ---- y-stage lane constants ----
    int tp = lane >> 3, ug = lane & 7;

    // persistent y acc (f32x2 over u-pairs), init with ybias
    ull acc2[4][2][2];
    #pragma unroll
    for (int oq = 0; oq < 4; oq++) {
        const float* yb = g_ybias + (size_t)(n*OO + obase + 4*w + oq)*VV;
        #pragma unroll
        for (int p = 0; p < 2; p++) {
            int u0 = 4*ug + 2*p;
            float y0 = (u0   < VV) ? yb[u0]   : 0.f;
            float y1 = (u0+1 < VV) ? yb[u0+1] : 0.f;
            ull ybp = pk2(y0, y1);
            acc2[oq][0][p] = ybp; acc2[oq][1][p] = ybp;
        }
    }
    __syncthreads();

    for (int s = 0; s < SS; s++) {
        // ---- v-stage: 8 o's x 2 tv-pairs; w3 via constant port ----
        ull acc[8][2];
        #pragma unroll
        for (int i = 0; i < 8; i++) { acc[i][0] = 0ull; acc[i][1] = 0ull; }

        int wbase = (s*CC)*OO + obase + 8*q;
        #pragma unroll 4
        for (int c = 0; c < CC; c++) {
            float4 wA4 = *(const float4*)(c_w3t + wbase + c*OO);
            float4 wB4 = *(const float4*)(c_w3t + wbase + c*OO + 4);
            const float* xr = xs + c*TVW;
            ull xA = *(const ull*)(xr + offA);
            ull xB = *(const ull*)(xr + offB);
            ull w0 = pk2(wA4.x, wA4.x), w1 = pk2(wA4.y, wA4.y);
            ull w2 = pk2(wA4.z, wA4.z), w3s = pk2(wA4.w, wA4.w);
            ull w4s = pk2(wB4.x, wB4.x), w5 = pk2(wB4.y, wB4.y);
            ull w6 = pk2(wB4.z, wB4.z), w7 = pk2(wB4.w, wB4.w);
            acc[0][0]=fma2(w0,xA,acc[0][0]);  acc[0][1]=fma2(w0,xB,acc[0][1]);
            acc[1][0]=fma2(w1,xA,acc[1][0]);  acc[1][1]=fma2(w1,xB,acc[1][1]);
            acc[2][0]=fma2(w2,xA,acc[2][0]);  acc[2][1]=fma2(w2,xB,acc[2][1]);
            acc[3][0]=fma2(w3s,xA,acc[3][0]); acc[3][1]=fma2(w3s,xB,acc[3][1]);
            acc[4][0]=fma2(w4s,xA,acc[4][0]); acc[4][1]=fma2(w4s,xB,acc[4][1]);
            acc[5][0]=fma2(w5,xA,acc[5][0]);  acc[5][1]=fma2(w5,xB,acc[5][1]);
            acc[6][0]=fma2(w6,xA,acc[6][0]);  acc[6][1]=fma2(w6,xB,acc[6][1]);
            acc[7][0]=fma2(w7,xA,acc[7][0]);  acc[7][1]=fma2(w7,xB,acc[7][1]);
        }

        __syncthreads();   // prior y-stage reads of vt complete
        // ---- dump vT[o_loc][v][t] ----
        #pragma unroll
        for (int i = 0; i < 8; i++) {
            float* d = vt + (8*q + i) * OSTR;
            float lo, hi;
            upk2(acc[i][0], lo, hi);
            d[sA0] = lo; d[sA1] = hi;
            if (hasB) {
                upk2(acc[i][1], lo, hi);
                d[sB0] = lo; d[sB1] = hi;
            }
        }
        __syncthreads();

        // ---- y-stage: 4 oq att streams, fp16 att loads (LDG.64) ----
        const float* dvp0 = vt + (4*w + 0)*OSTR + 2*tp;
        const float* dvp1 = vt + (4*w + 1)*OSTR + 2*tp;
        const float* dvp2 = vt + (4*w + 2)*OSTR + 2*tp;
        const float* dvp3 = vt + (4*w + 3)*OSTR + 2*tp;
        const __half* agb = g_atth + (size_t)((n*SS + s)*OO + obase + 4*w)*AOS + 4*ug;
        #pragma unroll
        for (int v = 0; v < VV; v++) {
            uint2 r0 = *(const uint2*)(agb + 0*AOS + v*UPAD);
            uint2 r1 = *(const uint2*)(agb + 1*AOS + v*UPAD);
            uint2 r2 = *(const uint2*)(agb + 2*AOS + v*UPAD);
            uint2 r3 = *(const uint2*)(agb + 3*AOS + v*UPAD);
            float2 vb0 = *(const float2*)(dvp0 + v*VTS);
            float2 vb1 = *(const float2*)(dvp1 + v*VTS);
            float2 vb2 = *(const float2*)(dvp2 + v*VTS);
            float2 vb3 = *(const float2*)(dvp3 + v*VTS);

            ull atx, aty, va, vbb;
            atx = h2f2(r0.x); aty = h2f2(r0.y);
            va = pk2(vb0.x, vb0.x); vbb = pk2(vb0.y, vb0.y);
            acc2[0][0][0] = fma2(atx, va,  acc2[0][0][0]);
            acc2[0][0][1] = fma2(aty, va,  acc2[0][0][1]);
            acc2[0][1][0] = fma2(atx, vbb, acc2[0][1][0]);
            acc2[0][1][1] = fma2(aty, vbb, acc2[0][1][1]);
            atx = h2f2(r1.x); aty = h2f2(r1.y);
            va = pk2(vb1.x, vb1.x); vbb = pk2(vb1.y, vb1.y);
            acc2[1][0][0] = fma2(atx, va,  acc2[1][0][0]);
            acc2[1][0][1] = fma2(aty, va,  acc2[1][0][1]);
            acc2[1][1][0] = fma2(atx, vbb, acc2[1][1][0]);
            acc2[1][1][1] = fma2(aty, vbb, acc2[1][1][1]);
            atx = h2f2(r2.x); aty = h2f2(r2.y);
            va = pk2(vb2.x, vb2.x); vbb = pk2(vb2.y, vb2.y);
            acc2[2][0][0] = fma2(atx, va,  acc2[2][0][0]);
            acc2[2][0][1] = fma2(aty, va,  acc2[2][0][1]);
            acc2[2][1][0] = fma2(atx, vbb, acc2[2][1][0]);
            acc2[2][1][1] = fma2(aty, vbb, acc2[2][1][1]);
            atx = h2f2(r3.x); aty = h2f2(r3.y);
            va = pk2(vb3.x, vb3.x); vbb = pk2(vb3.y, vb3.y);
            acc2[3][0][0] = fma2(atx, va,  acc2[3][0][0]);
            acc2[3][0][1] = fma2(aty, va,  acc2[3][0][1]);
            acc2[3][1][0] = fma2(atx, vbb, acc2[3][1][0]);
            acc2[3][1][1] = fma2(aty, vbb, acc2[3][1][1]);
        }
    }

    // ---- epilogue: write y (fp16), accumulate BN stats (fp32 exact) ----
    #pragma unroll
    for (int oq = 0; oq < 4; oq++) {
        int o = obase + 4*w + oq;
        float ps = 0.f, pss = 0.f;
        #pragma unroll
        for (int j = 0; j < 2; j++) {
            int t = 2*tp + j;
            float uv0, uv1, uv2, uv3;
            upk2(acc2[oq][j][0], uv0, uv1);
            upk2(acc2[oq][j][1], uv2, uv3);
            float vals[4] = {uv0, uv1, uv2, uv3};
            __half* yp = g_yh + ((size_t)(n*OO + o)*TT + t0 + t)*VV;
            #pragma unroll
            for (int i = 0; i < 4; i++) {
                int u = 4*ug + i;
                if (u < VV) {
                    yp[u] = __float2half(vals[i]);
                    ps  += vals[i];
                    pss += vals[i]*vals[i];
                }
            }
        }
        #pragma unroll
        for (int off = 16; off > 0; off >>= 1) {
            ps  += __shfl_xor_sync(0xffffffffu, ps,  off);
            pss += __shfl_xor_sync(0xffffffffu, pss, off);
        }
        if (lane == 0) {
            atomicAdd(&g_sum[o],   ps);
            atomicAdd(&g_sumsq[o], pss);
        }
    }
}

// ---------------------------------------------------------------------------
// Kernel 5: out = relu(y) + y*scale + shift + x (BN params derived in-block).
// ---------------------------------------------------------------------------
__global__ void k_final(const float* __restrict__ x, float* __restrict__ out,
                        const float* __restrict__ gamma, const float* __restrict__ beta) {
    __shared__ float s_sc[OO], s_sh[OO];
    int tid = threadIdx.x;
    if (tid < OO) {
        float cnt = (float)(NN*TT*VV);
        float mu  = g_sum[tid] / cnt;
        float var = g_sumsq[tid] / cnt - mu*mu;
        float sc  = gamma[tid] * rsqrtf(var + EPSV);
        s_sc[tid] = sc;
        s_sh[tid] = beta[tid] - mu*sc;
    }
    __syncthreads();

    const int total4 = NN*OO*TT*VV / 4;
    for (int i = blockIdx.x*blockDim.x + tid; i < total4; i += gridDim.x*blockDim.x) {
        int c = (i / (TT*VV/4)) % OO;
        float sc = s_sc[c], sh = s_sh[c];
        uint2 raw = ((const uint2*)g_yh)[i];      // 4 halves, 8B aligned
        __half2 h0 = *reinterpret_cast<__half2*>(&raw.x);
        __half2 h1 = *reinterpret_cast<__half2*>(&raw.y);
        float2 f0 = __half22float2(h0);
        float2 f1 = __half22float2(h1);
        float4 x4 = ((const float4*)x)[i];
        float4 r;
        r.x = fmaxf(f0.x, 0.f) + fmaf(f0.x, sc, sh) + x4.x;
        r.y = fmaxf(f0.y, 0.f) + fmaf(f0.y, sc, sh) + x4.y;
        r.z = fmaxf(f1.x, 0.f) + fmaf(f1.x, sc, sh) + x4.z;
        r.w = fmaxf(f1.y, 0.f) + fmaf(f1.y, sc, sh) + x4.w;
        ((float4*)out)[i] = r;
    }
}

// ---------------------------------------------------------------------------
extern "C" void kernel_launch(void* const* d_in, const int* in_sizes, int n_in,
                              void* d_out, int out_size) {
    (void)in_sizes; (void)n_in; (void)out_size;
    const float* x     = (const float*)d_in[0];
    const float* A     = (const float*)d_in[1];
    const float* w1    = (const float*)d_in[2];
    const float* b1    = (const float*)d_in[3];
    const float* w2    = (const float*)d_in[4];
    const float* b2    = (const float*)d_in[5];
    const float* w3    = (const float*)d_in[6];
    const float* b3    = (const float*)d_in[7];
    const float* w4    = (const float*)d_in[8];
    const float* b4    = (const float*)d_in[9];
    const float* alpha = (const float*)d_in[10];
    const float* gamma = (const float*)d_in[11];
    const float* beta  = (const float*)d_in[12];
    float* out = (float*)d_out;

    static const int smem_bytes = SMEM_FLOATS * (int)sizeof(float);
    cudaFuncSetAttribute(k_main, cudaFuncAttributeMaxDynamicSharedMemorySize, smem_bytes);

    void* w3t_dev = nullptr;
    cudaGetSymbolAddress(&w3t_dev, g_w3t);

    k_xm   <<< NN*CC, 256 >>>(x, w3);
    cudaMemcpyToSymbolAsync(c_w3t, w3t_dev, SS*CC*OO*sizeof(float), 0,
                            cudaMemcpyDeviceToDevice, 0);
    k_att  <<< NN*SS*4, 256 >>>(w1, b1, w2, b2, w4, b4, alpha, A);
    k_ybias<<< NN*8, 256 >>>(b3);
    k_main <<< NN*NTB*2, 256, smem_bytes >>>(x);
    k_final<<< 4096, 256 >>>(x, out, gamma, beta);
}

// round 15
// speedup vs baseline: 1.5559x; 1.4386x over previous
#include <cuda_runtime.h>
#include <cuda_fp16.h>

#define NN 32
#define CC 64
#define OO 64
#define TT 512
#define VV 25
#define SS 3
#define RR 32
#define EPSV 1e-5f
#define TB 8            // t-tile per block
#define NTB (TT/TB)     // 64
#define TVW (TB*VV)     // 200
#define UPAD 32         // att u-row pad (32 halves = 64B rows)
#define AOS (VV*UPAD)   // 800 halves per (n,s,o)
#define VTS 10          // vT row stride: [v][t] stride 10
#define OSTR (VV*VTS)   // 250 floats per o in vt
#define OHALF 32        // o's per block
#define XTS 74          // xsT row stride in halves (37 words, gcd(37,32)=1)
#define W3S 72          // w3s row stride in halves (36 words)

// ---- scratch ----
__device__ __align__(16) float  g_xm[NN*CC*VV];
__device__ __align__(16) __half g_atth[NN*SS*OO*AOS]; // att fp16, transposed [v][u]
__device__ __align__(16) float  g_ybias[NN*OO*VV];
__device__ __align__(16) __half g_yh[NN*OO*TT*VV];    // y in fp16
__device__ float g_sum[OO], g_sumsq[OO];

// ---- f32x2 helpers ----
typedef unsigned long long ull;
__device__ __forceinline__ ull pk2(float a, float b) {
    ull r; asm("mov.b64 %0, {%1, %2};" : "=l"(r) : "f"(a), "f"(b)); return r;
}
__device__ __forceinline__ void upk2(ull p, float& a, float& b) {
    asm("mov.b64 {%0, %1}, %2;" : "=f"(a), "=f"(b) : "l"(p));
}
__device__ __forceinline__ ull fma2(ull a, ull b, ull c) {
    ull d; asm("fma.rn.f32x2 %0, %1, %2, %3;" : "=l"(d) : "l"(a), "l"(b), "l"(c)); return d;
}
__device__ __forceinline__ ull h2f2(unsigned h) {
    __half2 hh = *reinterpret_cast<__half2*>(&h);
    float2 f = __half22float2(hh);
    return pk2(f.x, f.y);
}
// m16n8k16 fp16 MMA, fp32 accum
__device__ __forceinline__ void mma16816(float& d0, float& d1, float& d2, float& d3,
                                         unsigned a0, unsigned a1, unsigned a2, unsigned a3,
                                         unsigned b0, unsigned b1) {
    asm volatile("mma.sync.aligned.m16n8k16.row.col.f32.f16.f16.f32 "
                 "{%0,%1,%2,%3}, {%4,%5,%6,%7}, {%8,%9}, {%0,%1,%2,%3};"
                 : "+f"(d0), "+f"(d1), "+f"(d2), "+f"(d3)
                 : "r"(a0), "r"(a1), "r"(a2), "r"(a3), "r"(b0), "r"(b1));
}

// ---------------------------------------------------------------------------
// Kernel 1: xm mean over T (coalesced, warp-per-t-chunk).
// ---------------------------------------------------------------------------
__global__ void k_xm(const float* __restrict__ x) {
    int bid = blockIdx.x;              // (n*CC + c), 2048 blocks
    int tid = threadIdx.x, w = tid >> 5, lane = tid & 31;
    __shared__ float part[8][VV];
    const float* base = x + (size_t)bid * (TT*VV);
    if (lane < VV) {
        const float* p = base + (w*64)*VV + lane;
        float a0=0.f, a1=0.f, a2=0.f, a3=0.f;
        #pragma unroll 4
        for (int t = 0; t < 64; t += 4) {
            a0 += p[(t+0)*VV]; a1 += p[(t+1)*VV];
            a2 += p[(t+2)*VV]; a3 += p[(t+3)*VV];
        }
        part[w][lane] = (a0+a1)+(a2+a3);
    }
    __syncthreads();
    if (tid < VV) {
        float s2 = 0.f;
        #pragma unroll
        for (int ww = 0; ww < 8; ww++) s2 += part[ww][tid];
        g_xm[bid*VV + tid] = s2 * (1.0f/(float)TT);
    }
}

// ---------------------------------------------------------------------------
// Kernel 2 (o-split x4): attention tensor -> fp16, transposed+padded
// ---------------------------------------------------------------------------
#define OSL 16
__global__ void k_att(const float* __restrict__ w1, const float* __restrict__ b1,
                      const float* __restrict__ w2, const float* __restrict__ b2,
                      const float* __restrict__ w4, const float* __restrict__ b4,
                      const float* __restrict__ alpha, const float* __restrict__ A) {
    int og = blockIdx.x & 3;
    int ns = blockIdx.x >> 2;
    int n = ns / SS, s = ns % SS;
    __shared__ float xm_sm[CC*VV];
    __shared__ float q_sm[RR*VV];
    __shared__ float k_sm[RR*VV];
    __shared__ float w4_sm[OSL*RR];
    __shared__ float b4_sm[OSL];
    int tid = threadIdx.x;

    for (int i = tid; i < CC*VV; i += blockDim.x) xm_sm[i] = g_xm[n*CC*VV + i];
    for (int i = tid; i < OSL*RR; i += blockDim.x) w4_sm[i] = w4[s*OO*RR + og*OSL*RR + i];
    if (tid < OSL) b4_sm[tid] = b4[s*OO + og*OSL + tid];
    __syncthreads();

    for (int e = tid; e < RR*VV; e += blockDim.x) {
        int r = e / VV, v = e % VV;
        const float* w1r = w1 + (s*RR + r)*CC;
        const float* w2r = w2 + (s*RR + r)*CC;
        float accq = b1[s*RR + r], acck = b2[s*RR + r];
        #pragma unroll 8
        for (int c = 0; c < CC; c++) {
            float xv = xm_sm[c*VV + v];
            accq = fmaf(w1r[c], xv, accq);
            acck = fmaf(w2r[c], xv, acck);
        }
        q_sm[e] = accq; k_sm[e] = acck;
    }
    __syncthreads();

    float al = alpha[s];
    for (int uv = tid; uv < VV*VV; uv += blockDim.x) {
        int u = uv / VV, v = uv % VV;
        float rel[RR];
        #pragma unroll
        for (int r = 0; r < RR; r++)
            rel[r] = fmaxf(q_sm[r*VV + u] - k_sm[r*VV + v], 0.f);
        float Auv = A[(s*VV + u)*VV + v];
        __half* outp = g_atth + (size_t)((n*SS + s)*OO + og*OSL) * AOS + v*UPAD + u;
        for (int o = 0; o < OSL; o++) {
            float acc = 0.f;
            #pragma unroll
            for (int r = 0; r < RR; r++)
                acc = fmaf(w4_sm[o*RR + r], rel[r], acc);
            outp[o*AOS] = __float2half(al*(acc + b4_sm[o]) + Auv);
        }
    }
}

// ---------------------------------------------------------------------------
// Kernel 3: ybias via one warp per (n,o); zeroes BN stats.
// ---------------------------------------------------------------------------
__global__ void k_ybias(const float* __restrict__ b3) {
    int n   = blockIdx.x >> 3;
    int oct = blockIdx.x & 7;
    int tid = threadIdx.x, w = tid >> 5, lane = tid & 31;
    if (blockIdx.x == 0) {
        if (tid < OO)             g_sum[tid] = 0.f;
        else if (tid < 2*OO)      g_sumsq[tid - OO] = 0.f;
    }
    int o = oct*8 + w;
    float acc = 0.f;
    #pragma unroll
    for (int s = 0; s < SS; s++) {
        const __half* ap = g_atth + (size_t)((n*SS + s)*OO + o) * AOS + lane;
        float rs = 0.f;
        #pragma unroll
        for (int v = 0; v < VV; v++) rs += __half2float(ap[v*UPAD]);
        acc = fmaf(b3[s*OO + o], rs, acc);
    }
    if (lane < VV) g_ybias[(n*OO + o)*VV + lane] = acc;
}

// ---------------------------------------------------------------------------
// Kernel 4 (main): v-stage on TENSOR CORES (mma.sync m16n8k16 f16->f32);
// y-stage/epilogue identical to round 14 (proven).
// smem: xsT (fp16 x, transposed [tv][74]) | w3s (fp16 [s][32o][72]) | vt (fp32)
// ---------------------------------------------------------------------------
#define SM_XST_B (TVW*XTS*2)          // 29600
#define SM_W3S_B (SS*OHALF*W3S*2)     // 13824
#define SM_VT_B  (OHALF*OSTR*4)       // 32000
#define SMEM_BYTES (SM_XST_B + SM_W3S_B + SM_VT_B)   // 75424

__global__ void __launch_bounds__(256, 2)
k_main(const float* __restrict__ x, const float* __restrict__ w3g) {
    extern __shared__ char smb[];
    __half* xsT = (__half*)smb;
    __half* w3s = (__half*)(smb + SM_XST_B);
    float*  vt  = (float*)(smb + SM_XST_B + SM_W3S_B);

    int rem  = blockIdx.x % (NTB*2);
    int n    = blockIdx.x / (NTB*2);
    int tb   = rem >> 1;
    int obase = (rem & 1) * OHALF;
    int t0 = tb * TB;
    int tid = threadIdx.x, w = tid >> 5, lane = tid & 31;

    // ---- stage x transposed fp16: xsT[tv][c], row stride 74 halves ----
    if (tid < TVW) {
        const float* xr = x + (size_t)n*CC*TT*VV + t0*VV + tid;   // x[n][c][t0*VV+tv]
        __half* dst = xsT + tid*XTS;
        #pragma unroll 4
        for (int c = 0; c < CC; c += 2) {
            float f0 = xr[(size_t)c*TT*VV];
            float f1 = xr[(size_t)(c+1)*TT*VV];
            __half2 h = __floats2half2_rn(f0, f1);
            *reinterpret_cast<unsigned*>(dst + c) = *reinterpret_cast<unsigned*>(&h);
        }
    }
    // ---- stage w3 slice fp16: w3s[s][o_loc][c], row stride 72 halves ----
    for (int i = tid; i < SS*OHALF*CC; i += 256) {
        int s = i / (OHALF*CC), r2 = i % (OHALF*CC);
        int ol = r2 / CC, c = r2 % CC;
        w3s[s*(OHALF*W3S) + ol*W3S + c] =
            __float2half(w3g[((size_t)s*OO + obase + ol)*CC + c]);
    }

    // ---- y-stage lane constants ----
    int tp = lane >> 3, ug = lane & 7;
    // ---- mma lane constants ----
    int g = lane >> 2, r = lane & 3;

    // persistent y acc (f32x2 over u-pairs), init with ybias
    ull acc2[4][2][2];
    #pragma unroll
    for (int oq = 0; oq < 4; oq++) {
        const float* yb = g_ybias + (size_t)(n*OO + obase + 4*w + oq)*VV;
        #pragma unroll
        for (int p = 0; p < 2; p++) {
            int u0 = 4*ug + 2*p;
            float y0 = (u0   < VV) ? yb[u0]   : 0.f;
            float y1 = (u0+1 < VV) ? yb[u0+1] : 0.f;
            ull ybp = pk2(y0, y1);
            acc2[oq][0][p] = ybp; acc2[oq][1][p] = ybp;
        }
    }

    for (int s = 0; s < SS; s++) {
        __syncthreads();   // staging ready (s=0) / prior y-stage reads of vt done

        // ---- v-stage: tensor-core GEMM [32o x 64c] x [64c x 200tv] ----
        const __half* w3sp = w3s + s*(OHALF*W3S);
        #pragma unroll
        for (int ot = 0; ot < 2; ot++) {
            unsigned a[4][4];
            const __half* arow = w3sp + (ot*16 + g)*W3S + 2*r;
            #pragma unroll
            for (int kt = 0; kt < 4; kt++) {
                a[kt][0] = *(const unsigned*)(arow + kt*16);
                a[kt][1] = *(const unsigned*)(arow + 8*W3S + kt*16);
                a[kt][2] = *(const unsigned*)(arow + kt*16 + 8);
                a[kt][3] = *(const unsigned*)(arow + 8*W3S + kt*16 + 8);
            }
            for (int tvt = w; tvt < 25; tvt += 8) {
                float d0 = 0.f, d1 = 0.f, d2 = 0.f, d3 = 0.f;
                const __half* brow = xsT + (tvt*8 + g)*XTS + 2*r;
                #pragma unroll
                for (int kt = 0; kt < 4; kt++) {
                    unsigned b0 = *(const unsigned*)(brow + kt*16);
                    unsigned b1 = *(const unsigned*)(brow + kt*16 + 8);
                    mma16816(d0, d1, d2, d3,
                             a[kt][0], a[kt][1], a[kt][2], a[kt][3], b0, b1);
                }
                // dump D: rows o_loc = ot*16+g (+8); cols tv = tvt*8+2r (+1)
                int tv0 = tvt*8 + 2*r;
                int ti0 = tv0 / VV, v0 = tv0 - ti0*VV;
                int tv1 = tv0 + 1;
                int ti1 = tv1 / VV, v1 = tv1 - ti1*VV;
                float* dlo = vt + (ot*16 + g)*OSTR;
                float* dhi = dlo + 8*OSTR;
                dlo[v0*VTS + ti0] = d0;  dlo[v1*VTS + ti1] = d1;
                dhi[v0*VTS + ti0] = d2;  dhi[v1*VTS + ti1] = d3;
            }
        }
        __syncthreads();   // vt complete

        // ---- y-stage: 4 oq att streams, fp16 att loads (round-14 proven) ----
        const float* dvp0 = vt + (4*w + 0)*OSTR + 2*tp;
        const float* dvp1 = vt + (4*w + 1)*OSTR + 2*tp;
        const float* dvp2 = vt + (4*w + 2)*OSTR + 2*tp;
        const float* dvp3 = vt + (4*w + 3)*OSTR + 2*tp;
        const __half* agb = g_atth + (size_t)((n*SS + s)*OO + obase + 4*w)*AOS + 4*ug;
        #pragma unroll
        for (int v = 0; v < VV; v++) {
            uint2 r0 = *(const uint2*)(agb + 0*AOS + v*UPAD);
            uint2 r1 = *(const uint2*)(agb + 1*AOS + v*UPAD);
            uint2 r2 = *(const uint2*)(agb + 2*AOS + v*UPAD);
            uint2 r3 = *(const uint2*)(agb + 3*AOS + v*UPAD);
            float2 vb0 = *(const float2*)(dvp0 + v*VTS);
            float2 vb1 = *(const float2*)(dvp1 + v*VTS);
            float2 vb2 = *(const float2*)(dvp2 + v*VTS);
            float2 vb3 = *(const float2*)(dvp3 + v*VTS);

            ull atx, aty, va, vbb;
            atx = h2f2(r0.x); aty = h2f2(r0.y);
            va = pk2(vb0.x, vb0.x); vbb = pk2(vb0.y, vb0.y);
            acc2[0][0][0] = fma2(atx, va,  acc2[0][0][0]);
            acc2[0][0][1] = fma2(aty, va,  acc2[0][0][1]);
            acc2[0][1][0] = fma2(atx, vbb, acc2[0][1][0]);
            acc2[0][1][1] = fma2(aty, vbb, acc2[0][1][1]);
            atx = h2f2(r1.x); aty = h2f2(r1.y);
            va = pk2(vb1.x, vb1.x); vbb = pk2(vb1.y, vb1.y);
            acc2[1][0][0] = fma2(atx, va,  acc2[1][0][0]);
            acc2[1][0][1] = fma2(aty, va,  acc2[1][0][1]);
            acc2[1][1][0] = fma2(atx, vbb, acc2[1][1][0]);
            acc2[1][1][1] = fma2(aty, vbb, acc2[1][1][1]);
            atx = h2f2(r2.x); aty = h2f2(r2.y);
            va = pk2(vb2.x, vb2.x); vbb = pk2(vb2.y, vb2.y);
            acc2[2][0][0] = fma2(atx, va,  acc2[2][0][0]);
            acc2[2][0][1] = fma2(aty, va,  acc2[2][0][1]);
            acc2[2][1][0] = fma2(atx, vbb, acc2[2][1][0]);
            acc2[2][1][1] = fma2(aty, vbb, acc2[2][1][1]);
            atx = h2f2(r3.x); aty = h2f2(r3.y);
            va = pk2(vb3.x, vb3.x); vbb = pk2(vb3.y, vb3.y);
            acc2[3][0][0] = fma2(atx, va,  acc2[3][0][0]);
            acc2[3][0][1] = fma2(aty, va,  acc2[3][0][1]);
            acc2[3][1][0] = fma2(atx, vbb, acc2[3][1][0]);
            acc2[3][1][1] = fma2(aty, vbb, acc2[3][1][1]);
        }
    }

    // ---- epilogue: write y (fp16), accumulate BN stats (fp32 exact) ----
    #pragma unroll
    for (int oq = 0; oq < 4; oq++) {
        int o = obase + 4*w + oq;
        float ps = 0.f, pss = 0.f;
        #pragma unroll
        for (int j = 0; j < 2; j++) {
            int t = 2*tp + j;
            float uv0, uv1, uv2, uv3;
            upk2(acc2[oq][j][0], uv0, uv1);
            upk2(acc2[oq][j][1], uv2, uv3);
            float vals[4] = {uv0, uv1, uv2, uv3};
            __half* yp = g_yh + ((size_t)(n*OO + o)*TT + t0 + t)*VV;
            #pragma unroll
            for (int i = 0; i < 4; i++) {
                int u = 4*ug + i;
                if (u < VV) {
                    yp[u] = __float2half(vals[i]);
                    ps  += vals[i];
                    pss += vals[i]*vals[i];
                }
            }
        }
        #pragma unroll
        for (int off = 16; off > 0; off >>= 1) {
            ps  += __shfl_xor_sync(0xffffffffu, ps,  off);
            pss += __shfl_xor_sync(0xffffffffu, pss, off);
        }
        if (lane == 0) {
            atomicAdd(&g_sum[o],   ps);
            atomicAdd(&g_sumsq[o], pss);
        }
    }
}

// ---------------------------------------------------------------------------
// Kernel 5: out = relu(y) + y*scale + shift + x (BN params derived in-block).
// ---------------------------------------------------------------------------
__global__ void k_final(const float* __restrict__ x, float* __restrict__ out,
                        const float* __restrict__ gamma, const float* __restrict__ beta) {
    __shared__ float s_sc[OO], s_sh[OO];
    int tid = threadIdx.x;
    if (tid < OO) {
        float cnt = (float)(NN*TT*VV);
        float mu  = g_sum[tid] / cnt;
        float var = g_sumsq[tid] / cnt - mu*mu;
        float sc  = gamma[tid] * rsqrtf(var + EPSV);
        s_sc[tid] = sc;
        s_sh[tid] = beta[tid] - mu*sc;
    }
    __syncthreads();

    const int total4 = NN*OO*TT*VV / 4;
    for (int i = blockIdx.x*blockDim.x + tid; i < total4; i += gridDim.x*blockDim.x) {
        int c = (i / (TT*VV/4)) % OO;
        float sc = s_sc[c], sh = s_sh[c];
        uint2 raw = ((const uint2*)g_yh)[i];
        __half2 h0 = *reinterpret_cast<__half2*>(&raw.x);
        __half2 h1 = *reinterpret_cast<__half2*>(&raw.y);
        float2 f0 = __half22float2(h0);
        float2 f1 = __half22float2(h1);
        float4 x4 = ((const float4*)x)[i];
        float4 r;
        r.x = fmaxf(f0.x, 0.f) + fmaf(f0.x, sc, sh) + x4.x;
        r.y = fmaxf(f0.y, 0.f) + fmaf(f0.y, sc, sh) + x4.y;
        r.z = fmaxf(f1.x, 0.f) + fmaf(f1.x, sc, sh) + x4.z;
        r.w = fmaxf(f1.y, 0.f) + fmaf(f1.y, sc, sh) + x4.w;
        ((float4*)out)[i] = r;
    }
}

// ---------------------------------------------------------------------------
extern "C" void kernel_launch(void* const* d_in, const int* in_sizes, int n_in,
                              void* d_out, int out_size) {
    (void)in_sizes; (void)n_in; (void)out_size;
    const float* x     = (const float*)d_in[0];
    const float* A     = (const float*)d_in[1];
    const float* w1    = (const float*)d_in[2];
    const float* b1    = (const float*)d_in[3];
    const float* w2    = (const float*)d_in[4];
    const float* b2    = (const float*)d_in[5];
    const float* w3    = (const float*)d_in[6];
    const float* b3    = (const float*)d_in[7];
    const float* w4    = (const float*)d_in[8];
    const float* b4    = (const float*)d_in[9];
    const float* alpha = (const float*)d_in[10];
    const float* gamma = (const float*)d_in[11];
    const float* beta  = (const float*)d_in[12];
    float* out = (float*)d_out;

    cudaFuncSetAttribute(k_main, cudaFuncAttributeMaxDynamicSharedMemorySize, SMEM_BYTES);

    k_xm   <<< NN*CC, 256 >>>(x);
    k_att  <<< NN*SS*4, 256 >>>(w1, b1, w2, b2, w4, b4, alpha, A);
    k_ybias<<< NN*8, 256 >>>(b3);
    k_main <<< NN*NTB*2, 256, SMEM_BYTES >>>(x, w3);
    k_final<<< 4096, 256 >>>(x, out, gamma, beta);
}

// round 16
// speedup vs baseline: 1.6546x; 1.0635x over previous
#include <cuda_runtime.h>
#include <cuda_fp16.h>

#define NN 32
#define CC 64
#define OO 64
#define TT 512
#define VV 25
#define SS 3
#define RR 32
#define EPSV 1e-5f
#define TB 8            // t-tile per block
#define NTB (TT/TB)     // 64
#define TVW (TB*VV)     // 200
#define UPAD 32         // att v-row width (halves)
#define AOS2 (32*UPAD)  // 1024 halves per (n,s,o): 32 padded u-rows x 32 v
#define OHALF 32        // o's per block
#define XTS 74          // xsT row stride in halves (37 words, gcd(37,32)=1)
#define W3S 72          // w3s row stride in halves
#define VSTR 40         // vth t-row stride in halves (20 words -> conflict-free B frags)
#define OVS (TB*VSTR)   // 320 halves per o in vth

// ---- scratch ----
__device__ __align__(16) float  g_xm[NN*CC*VV];
__device__ __align__(16) __half g_atth[NN*SS*OO*AOS2]; // att fp16 [u][v], pads zero
__device__ __align__(16) float  g_ybias[NN*OO*VV];
__device__ __align__(16) __half g_yh[NN*OO*TT*VV];     // y in fp16
__device__ float g_sum[OO], g_sumsq[OO];

// ---- helpers ----
typedef unsigned long long ull;
__device__ __forceinline__ void mma16816(float& d0, float& d1, float& d2, float& d3,
                                         unsigned a0, unsigned a1, unsigned a2, unsigned a3,
                                         unsigned b0, unsigned b1) {
    asm volatile("mma.sync.aligned.m16n8k16.row.col.f32.f16.f16.f32 "
                 "{%0,%1,%2,%3}, {%4,%5,%6,%7}, {%8,%9}, {%0,%1,%2,%3};"
                 : "+f"(d0), "+f"(d1), "+f"(d2), "+f"(d3)
                 : "r"(a0), "r"(a1), "r"(a2), "r"(a3), "r"(b0), "r"(b1));
}

// ---------------------------------------------------------------------------
// Kernel 1: xm mean over T (coalesced, warp-per-t-chunk).
// ---------------------------------------------------------------------------
__global__ void k_xm(const float* __restrict__ x) {
    int bid = blockIdx.x;              // (n*CC + c)
    int tid = threadIdx.x, w = tid >> 5, lane = tid & 31;
    __shared__ float part[8][VV];
    const float* base = x + (size_t)bid * (TT*VV);
    if (lane < VV) {
        const float* p = base + (w*64)*VV + lane;
        float a0=0.f, a1=0.f, a2=0.f, a3=0.f;
        #pragma unroll 4
        for (int t = 0; t < 64; t += 4) {
            a0 += p[(t+0)*VV]; a1 += p[(t+1)*VV];
            a2 += p[(t+2)*VV]; a3 += p[(t+3)*VV];
        }
        part[w][lane] = (a0+a1)+(a2+a3);
    }
    __syncthreads();
    if (tid < VV) {
        float s2 = 0.f;
        #pragma unroll
        for (int ww = 0; ww < 8; ww++) s2 += part[ww][tid];
        g_xm[bid*VV + tid] = s2 * (1.0f/(float)TT);
    }
}

// ---------------------------------------------------------------------------
// Kernel 2 (o-split x4): attention tensor -> fp16, ROW-major [u][32v]
// ---------------------------------------------------------------------------
#define OSL 16
__global__ void k_att(const float* __restrict__ w1, const float* __restrict__ b1,
                      const float* __restrict__ w2, const float* __restrict__ b2,
                      const float* __restrict__ w4, const float* __restrict__ b4,
                      const float* __restrict__ alpha, const float* __restrict__ A) {
    int og = blockIdx.x & 3;
    int ns = blockIdx.x >> 2;
    int n = ns / SS, s = ns % SS;
    __shared__ float xm_sm[CC*VV];
    __shared__ float q_sm[RR*VV];
    __shared__ float k_sm[RR*VV];
    __shared__ float w4_sm[OSL*RR];
    __shared__ float b4_sm[OSL];
    int tid = threadIdx.x;

    for (int i = tid; i < CC*VV; i += blockDim.x) xm_sm[i] = g_xm[n*CC*VV + i];
    for (int i = tid; i < OSL*RR; i += blockDim.x) w4_sm[i] = w4[s*OO*RR + og*OSL*RR + i];
    if (tid < OSL) b4_sm[tid] = b4[s*OO + og*OSL + tid];
    __syncthreads();

    for (int e = tid; e < RR*VV; e += blockDim.x) {
        int r = e / VV, v = e % VV;
        const float* w1r = w1 + (s*RR + r)*CC;
        const float* w2r = w2 + (s*RR + r)*CC;
        float accq = b1[s*RR + r], acck = b2[s*RR + r];
        #pragma unroll 8
        for (int c = 0; c < CC; c++) {
            float xv = xm_sm[c*VV + v];
            accq = fmaf(w1r[c], xv, accq);
            acck = fmaf(w2r[c], xv, acck);
        }
        q_sm[e] = accq; k_sm[e] = acck;
    }
    __syncthreads();

    float al = alpha[s];
    for (int uv = tid; uv < VV*VV; uv += blockDim.x) {
        int u = uv / VV, v = uv % VV;
        float rel[RR];
        #pragma unroll
        for (int r = 0; r < RR; r++)
            rel[r] = fmaxf(q_sm[r*VV + u] - k_sm[r*VV + v], 0.f);
        float Auv = A[(s*VV + u)*VV + v];
        __half* outp = g_atth + (size_t)((n*SS + s)*OO + og*OSL) * AOS2 + u*UPAD + v;
        for (int o = 0; o < OSL; o++) {
            float acc = 0.f;
            #pragma unroll
            for (int r = 0; r < RR; r++)
                acc = fmaf(w4_sm[o*RR + r], rel[r], acc);
            outp[o*AOS2] = __float2half(al*(acc + b4_sm[o]) + Auv);
        }
    }
}

// ---------------------------------------------------------------------------
// Kernel 3: ybias via one warp per (n,o); zeroes BN stats. (att now [u][v])
// ---------------------------------------------------------------------------
__global__ void k_ybias(const float* __restrict__ b3) {
    int n   = blockIdx.x >> 3;
    int oct = blockIdx.x & 7;
    int tid = threadIdx.x, w = tid >> 5, lane = tid & 31;
    if (blockIdx.x == 0) {
        if (tid < OO)             g_sum[tid] = 0.f;
        else if (tid < 2*OO)      g_sumsq[tid - OO] = 0.f;
    }
    int o = oct*8 + w;
    if (lane < VV) {
        float acc = 0.f;
        #pragma unroll
        for (int s = 0; s < SS; s++) {
            const __half* ap = g_atth + (size_t)((n*SS + s)*OO + o) * AOS2 + lane*UPAD;
            float rs = 0.f;
            const uint4* p4 = (const uint4*)ap;
            #pragma unroll
            for (int j = 0; j < 3; j++) {        // v 0..23
                uint4 q = p4[j];
                unsigned qs[4] = {q.x, q.y, q.z, q.w};
                #pragma unroll
                for (int e = 0; e < 4; e++) {
                    __half2 h = *reinterpret_cast<__half2*>(&qs[e]);
                    float2 f = __half22float2(h);
                    rs += f.x + f.y;
                }
            }
            rs += __half2float(ap[24]);
            acc = fmaf(b3[s*OO + o], rs, acc);
        }
        g_ybias[(n*OO + o)*VV + lane] = acc;
    }
}

// ---------------------------------------------------------------------------
// Kernel 4 (main): BOTH stages on tensor cores.
// v-stage (R15-proven): [32o x 64c] x [64c x 200tv] via mma, D -> vth fp16.
// y-stage (new): per o, D[32u x 8t] += att[32u x 32v] @ vth[32v x 8t] via 4
//   mma each s; D fragments ARE the persistent y accumulators (ybias-init).
// smem: xsT fp16 [tv][74] | w3s fp16 [s][32o][72] | vth fp16 [o][t][40]
// ---------------------------------------------------------------------------
#define SM_XST_B (TVW*XTS*2)          // 29600
#define SM_W3S_B (SS*OHALF*W3S*2)     // 13824
#define SM_VTH_B (OHALF*OVS*2)        // 20480
#define SMEM_BYTES (SM_XST_B + SM_W3S_B + SM_VTH_B)   // 63904

__global__ void __launch_bounds__(256, 2)
k_main(const float* __restrict__ x, const float* __restrict__ w3g) {
    extern __shared__ char smb[];
    __half* xsT = (__half*)smb;
    __half* w3s = (__half*)(smb + SM_XST_B);
    __half* vth = (__half*)(smb + SM_XST_B + SM_W3S_B);

    int rem  = blockIdx.x % (NTB*2);
    int n    = blockIdx.x / (NTB*2);
    int tb   = rem >> 1;
    int obase = (rem & 1) * OHALF;
    int t0 = tb * TB;
    int tid = threadIdx.x, w = tid >> 5, lane = tid & 31;
    int g = lane >> 2, r = lane & 3;     // mma lane coords

    // ---- stage x transposed fp16: xsT[tv][c] ----
    if (tid < TVW) {
        const float* xr = x + (size_t)n*CC*TT*VV + t0*VV + tid;
        __half* dst = xsT + tid*XTS;
        #pragma unroll 4
        for (int c = 0; c < CC; c += 2) {
            float f0 = xr[(size_t)c*TT*VV];
            float f1 = xr[(size_t)(c+1)*TT*VV];
            __half2 h = __floats2half2_rn(f0, f1);
            *reinterpret_cast<unsigned*>(dst + c) = *reinterpret_cast<unsigned*>(&h);
        }
    }
    // ---- stage w3 slice fp16: w3s[s][o_loc][c] ----
    for (int i = tid; i < SS*OHALF*CC; i += 256) {
        int s = i / (OHALF*CC), r2 = i % (OHALF*CC);
        int ol = r2 / CC, c = r2 % CC;
        w3s[s*(OHALF*W3S) + ol*W3S + c] =
            __float2half(w3g[((size_t)s*OO + obase + ol)*CC + c]);
    }
    // ---- zero vth v-pads (v=25..31) once; dumps never touch them ----
    {
        int i = tid;              // 256 = 32o x 8t exactly
        __half* p = vth + (i >> 3)*OVS + (i & 7)*VSTR + VV;
        #pragma unroll
        for (int j = 0; j < 7; j++) p[j] = __float2half(0.f);
    }

    // ---- persistent y accumulators = D fragments, init with ybias ----
    // accD[oq][mtile][j]: j: (t=2r,u=m16+g)(t=2r+1,u)(t=2r,u+8)(t=2r+1,u+8)
    float accD[4][2][4];
    #pragma unroll
    for (int oq = 0; oq < 4; oq++) {
        const float* yb = g_ybias + (size_t)(n*OO + obase + 4*w + oq)*VV;
        #pragma unroll
        for (int m = 0; m < 2; m++) {
            int u0 = m*16 + g, u1 = u0 + 8;
            float y0 = (u0 < VV) ? yb[u0] : 0.f;
            float y1 = (u1 < VV) ? yb[u1] : 0.f;
            accD[oq][m][0] = y0; accD[oq][m][1] = y0;
            accD[oq][m][2] = y1; accD[oq][m][3] = y1;
        }
    }

    for (int s = 0; s < SS; s++) {
        __syncthreads();   // staging/pads ready (s=0) / prior y-stage reads of vth done

        // ---- v-stage: tensor GEMM [32o x 64c] x [64c x 200tv] (R15-proven) ----
        const __half* w3sp = w3s + s*(OHALF*W3S);
        #pragma unroll
        for (int ot = 0; ot < 2; ot++) {
            unsigned a[4][4];
            const __half* arow = w3sp + (ot*16 + g)*W3S + 2*r;
            #pragma unroll
            for (int kt = 0; kt < 4; kt++) {
                a[kt][0] = *(const unsigned*)(arow + kt*16);
                a[kt][1] = *(const unsigned*)(arow + 8*W3S + kt*16);
                a[kt][2] = *(const unsigned*)(arow + kt*16 + 8);
                a[kt][3] = *(const unsigned*)(arow + 8*W3S + kt*16 + 8);
            }
            for (int tvt = w; tvt < 25; tvt += 8) {
                float d0 = 0.f, d1 = 0.f, d2 = 0.f, d3 = 0.f;
                const __half* brow = xsT + (tvt*8 + g)*XTS + 2*r;
                #pragma unroll
                for (int kt = 0; kt < 4; kt++) {
                    unsigned b0 = *(const unsigned*)(brow + kt*16);
                    unsigned b1 = *(const unsigned*)(brow + kt*16 + 8);
                    mma16816(d0, d1, d2, d3,
                             a[kt][0], a[kt][1], a[kt][2], a[kt][3], b0, b1);
                }
                // dump D as fp16 into vth[o][t][v]
                int tv0 = tvt*8 + 2*r;
                int ti0 = tv0 / VV, v0 = tv0 - ti0*VV;
                int tv1 = tv0 + 1;
                int ti1 = tv1 / VV, v1 = tv1 - ti1*VV;
                __half* dlo = vth + (ot*16 + g)*OVS;
                __half* dhi = dlo + 8*OVS;
                dlo[ti0*VSTR + v0] = __float2half(d0);
                dlo[ti1*VSTR + v1] = __float2half(d1);
                dhi[ti0*VSTR + v0] = __float2half(d2);
                dhi[ti1*VSTR + v1] = __float2half(d3);
            }
        }
        __syncthreads();   // vth complete

        // ---- y-stage: per o, D[32u x 8t] += att[32u x 32v] @ vth[32v x 8t] ----
        #pragma unroll
        for (int oq = 0; oq < 4; oq++) {
            int o = obase + 4*w + oq;
            const __half* ab = g_atth + (size_t)((n*SS + s)*OO + o)*AOS2;
            const __half* vb = vth + (4*w + oq)*OVS + g*VSTR + 2*r;
            unsigned bk[2][2];
            #pragma unroll
            for (int k = 0; k < 2; k++) {
                bk[k][0] = *(const unsigned*)(vb + k*16);
                bk[k][1] = *(const unsigned*)(vb + k*16 + 8);
            }
            #pragma unroll
            for (int m = 0; m < 2; m++) {
                const __half* ar = ab + (m*16 + g)*UPAD + 2*r;
                #pragma unroll
                for (int k = 0; k < 2; k++) {
                    unsigned a0 = *(const unsigned*)(ar + k*16);
                    unsigned a1 = *(const unsigned*)(ar + 8*UPAD + k*16);
                    unsigned a2 = *(const unsigned*)(ar + k*16 + 8);
                    unsigned a3 = *(const unsigned*)(ar + 8*UPAD + k*16 + 8);
                    mma16816(accD[oq][m][0], accD[oq][m][1],
                             accD[oq][m][2], accD[oq][m][3],
                             a0, a1, a2, a3, bk[k][0], bk[k][1]);
                }
            }
        }
    }

    // ---- epilogue: write y (fp16) via D-fragment map, BN stats fp32 ----
    #pragma unroll
    for (int oq = 0; oq < 4; oq++) {
        int o = obase + 4*w + oq;
        float ps = 0.f, pss = 0.f;
        __half* yb = g_yh + ((size_t)(n*OO + o)*TT + t0)*VV;
        #pragma unroll
        for (int m = 0; m < 2; m++) {
            #pragma unroll
            for (int j = 0; j < 4; j++) {
                int u = m*16 + g + ((j >> 1) ? 8 : 0);
                int t = 2*r + (j & 1);
                float val = accD[oq][m][j];
                if (u < VV) {
                    yb[t*VV + u] = __float2half(val);
                    ps  += val;
                    pss += val*val;
                }
            }
        }
        #pragma unroll
        for (int off = 16; off > 0; off >>= 1) {
            ps  += __shfl_xor_sync(0xffffffffu, ps,  off);
            pss += __shfl_xor_sync(0xffffffffu, pss, off);
        }
        if (lane == 0) {
            atomicAdd(&g_sum[o],   ps);
            atomicAdd(&g_sumsq[o], pss);
        }
    }
}

// ---------------------------------------------------------------------------
// Kernel 5: out = relu(y) + y*scale + shift + x (BN params derived in-block).
// ---------------------------------------------------------------------------
__global__ void k_final(const float* __restrict__ x, float* __restrict__ out,
                        const float* __restrict__ gamma, const float* __restrict__ beta) {
    __shared__ float s_sc[OO], s_sh[OO];
    int tid = threadIdx.x;
    if (tid < OO) {
        float cnt = (float)(NN*TT*VV);
        float mu  = g_sum[tid] / cnt;
        float var = g_sumsq[tid] / cnt - mu*mu;
        float sc  = gamma[tid] * rsqrtf(var + EPSV);
        s_sc[tid] = sc;
        s_sh[tid] = beta[tid] - mu*sc;
    }
    __syncthreads();

    const int total4 = NN*OO*TT*VV / 4;
    for (int i = blockIdx.x*blockDim.x + tid; i < total4; i += gridDim.x*blockDim.x) {
        int c = (i / (TT*VV/4)) % OO;
        float sc = s_sc[c], sh = s_sh[c];
        uint2 raw = ((const uint2*)g_yh)[i];
        __half2 h0 = *reinterpret_cast<__half2*>(&raw.x);
        __half2 h1 = *reinterpret_cast<__half2*>(&raw.y);
        float2 f0 = __half22float2(h0);
        float2 f1 = __half22float2(h1);
        float4 x4 = ((const float4*)x)[i];
        float4 r;
        r.x = fmaxf(f0.x, 0.f) + fmaf(f0.x, sc, sh) + x4.x;
        r.y = fmaxf(f0.y, 0.f) + fmaf(f0.y, sc, sh) + x4.y;
        r.z = fmaxf(f1.x, 0.f) + fmaf(f1.x, sc, sh) + x4.z;
        r.w = fmaxf(f1.y, 0.f) + fmaf(f1.y, sc, sh) + x4.w;
        ((float4*)out)[i] = r;
    }
}

// ---------------------------------------------------------------------------
extern "C" void kernel_launch(void* const* d_in, const int* in_sizes, int n_in,
                              void* d_out, int out_size) {
    (void)in_sizes; (void)n_in; (void)out_size;
    const float* x     = (const float*)d_in[0];
    const float* A     = (const float*)d_in[1];
    const float* w1    = (const float*)d_in[2];
    const float* b1    = (const float*)d_in[3];
    const float* w2    = (const float*)d_in[4];
    const float* b2    = (const float*)d_in[5];
    const float* w3    = (const float*)d_in[6];
    const float* b3    = (const float*)d_in[7];
    const float* w4    = (const float*)d_in[8];
    const float* b4    = (const float*)d_in[9];
    const float* alpha = (const float*)d_in[10];
    const float* gamma = (const float*)d_in[11];
    const float* beta  = (const float*)d_in[12];
    float* out = (float*)d_out;

    cudaFuncSetAttribute(k_main, cudaFuncAttributeMaxDynamicSharedMemorySize, SMEM_BYTES);

    k_xm   <<< NN*CC, 256 >>>(x);
    k_att  <<< NN*SS*4, 256 >>>(w1, b1, w2, b2, w4, b4, alpha, A);
    k_ybias<<< NN*8, 256 >>>(b3);
    k_main <<< NN*NTB*2, 256, SMEM_BYTES >>>(x, w3);
    k_final<<< 4096, 256 >>>(x, out, gamma, beta);
}